// round 12
// baseline (speedup 1.0000x reference)
#include <cuda_runtime.h>
#include <cuda_fp16.h>
#include <cstdint>

#define N_ITEMS_K 1000000
#define FEAT_K    256
#define BAG_K     128
#define N_BAGS_K  50000
#define TILE_K    256
#define N_TILES_K ((N_ITEMS_K + TILE_K - 1) / TILE_K)   // 3907 (last tile 64 rows)
#define EPS_K     1e-5f

// ---------------- device scratch (statically zero-initialized) ----------------
__device__ float g_scratch[(size_t)N_BAGS_K * BAG_K + 2 * BAG_K];

// ---------------- shared memory layout (byte offsets) ----------------
// seg ids : [0, 1024)
// b vec   : [1024, 1536)
// W fp16  : [2048, 67584)      128 rows x 512 B, K-permuted + XOR swizzle
// x e-bufs: [67584, 165888)    3 x (256 rows x 128 B fp32 eighth), swizzled
// h fp16  : [165888, 231424)   256 rows x 256 B
#define SM_SEG   0
#define SM_B     1024
#define SM_W     2048
#define SM_X     67584
#define SM_H16   165888
#define SMEM_DYN 231424

__device__ __forceinline__ uint32_t smem_u32(const void* p) {
    uint32_t a;
    asm("{ .reg .u64 t; cvta.to.shared.u64 t, %1; cvt.u32.u64 %0, t; }" : "=r"(a) : "l"(p));
    return a;
}

__device__ __forceinline__ void ldsm4(uint32_t* r, uint32_t addr) {
    asm volatile("ldmatrix.sync.aligned.m8n8.x4.shared.b16 {%0,%1,%2,%3}, [%4];"
                 : "=r"(r[0]), "=r"(r[1]), "=r"(r[2]), "=r"(r[3]) : "r"(addr));
}

__device__ __forceinline__ void mma16816(float* c, const uint32_t* a,
                                         uint32_t b0, uint32_t b1) {
    asm volatile(
        "mma.sync.aligned.m16n8k16.row.col.f32.f16.f16.f32 "
        "{%0,%1,%2,%3},{%4,%5,%6,%7},{%8,%9},{%0,%1,%2,%3};"
        : "+f"(c[0]), "+f"(c[1]), "+f"(c[2]), "+f"(c[3])
        : "r"(a[0]), "r"(a[1]), "r"(a[2]), "r"(a[3]), "r"(b0), "r"(b1));
}

__device__ __forceinline__ void cp_async16z(uint32_t dst, const void* src, bool pred) {
    int sz = pred ? 16 : 0;
    asm volatile("cp.async.cg.shared.global [%0], [%1], 16, %2;"
                 :: "r"(dst), "l"(src), "r"(sz) : "memory");
}
#define CP_COMMIT() asm volatile("cp.async.commit_group;" ::: "memory")
#define CP_WAIT1()  asm volatile("cp.async.wait_group 1;" ::: "memory")
#define CP_WAIT0()  asm volatile("cp.async.wait_group 0;" ::: "memory")

__global__ void __launch_bounds__(512, 1)
fused_gemm_seg_kernel(const float* __restrict__ x, const float* __restrict__ W,
                      const float* __restrict__ bvec, const int* __restrict__ seg)
{
    extern __shared__ char sm[];
    const uint32_t sb = smem_u32(sm);
    const int tid  = threadIdx.x;
    const int lane = tid & 31;
    const int wid  = tid >> 5;

    int*   seg_s = (int*)(sm + SM_SEG);
    float* b_s   = (float*)(sm + SM_B);

    // staging constants: thread covers f4 = tid&7 of rows (tid>>3) + 64*it
    const int f4c = tid & 7, row0 = tid >> 3;
    const uint32_t dstc = (uint32_t)SM_X + (uint32_t)row0 * 128u
                        + ((uint32_t)(f4c ^ (row0 & 7)) << 4);
    const float4* xf4 = (const float4*)x;

    // cp.async one eighth (8 float4 per row) of tile t into buffer at bufoff
    auto issue_e = [&](int t, int e, uint32_t bufoff) {
        const int i0 = t * TILE_K;
        const float4* src = xf4 + (size_t)(i0 + row0) * 64 + e * 8 + f4c;
        uint32_t dst = sb + dstc + bufoff;
        #pragma unroll
        for (int it = 0; it < 4; it++) {
            cp_async16z(dst, src, i0 + row0 + it * 64 < N_ITEMS_K);
            dst += 8192u;       // 64 rows * 128 B
            src += 4096;        // 64 rows * 64 float4
        }
    };

    // ---- prologue eighths issued FIRST (latency hidden under W staging) ----
    issue_e(blockIdx.x, 0, 0);      CP_COMMIT();
    issue_e(blockIdx.x, 1, 32768);  CP_COMMIT();

    // ---- one-time: W -> fp16, K-permuted within each 16-group, swizzled ----
    for (int idx = tid; idx < BAG_K * FEAT_K; idx += 512) {
        int n = idx >> 8, k = idx & 255;
        int s = k >> 4, r = k & 15, tq = r >> 2, j = r & 3;
        int p = (j < 2) ? (2 * tq + j) : (8 + 2 * tq + (j - 2));
        int ks = 16 * s + p;
        uint32_t off = (uint32_t)n * 512u
                     + ((uint32_t)((ks >> 3) ^ (n & 7)) << 4)
                     + (uint32_t)(ks & 7) * 2u;
        *(__half*)(sm + SM_W + off) = __float2half_rn(W[idx]);
    }
    if (tid < BAG_K) b_s[tid] = bvec[tid];

    // warp tiling: 8 M-groups (32 rows each) x 2 N-halves (64 cols)
    const int mgrp = wid >> 1;
    const int nq   = wid & 1;

    // fragment lane geometry
    const int g  = lane >> 2;
    const int tq = lane & 3;
    const int b_ln = ((lane >> 4) << 3) + (lane & 7);
    const int b_ku = (lane >> 3) & 1;
    const int lane7 = lane & 7;
    const int R = mgrp * 32 + g;

    const uint32_t kb = (uint32_t)(b_ku ^ (lane7 & 1)) << 4;
    const uint32_t l6 = (uint32_t)(lane7 & 6);
    uint32_t Bb[4];
    #pragma unroll
    for (int j = 0; j < 4; j++)
        Bb[j] = sb + SM_W + (uint32_t)(nq * 64 + b_ln) * 512u + (uint32_t)j * 8192u + kb;
    uint32_t Arow[4];
    #pragma unroll
    for (int i = 0; i < 4; i++)
        Arow[i] = sb + SM_X + (uint32_t)(R + 8 * i) * 128u;
    const uint32_t xa0 = (uint32_t)(tq ^ g) << 4;     // sl=0 xor term; sl=1 = xa0^64

    __syncthreads();   // W/b staged (prologue cp.async already streaming)

    uint32_t rot = 0;  // buffer rotation: eighth e lives in buffer (rot+e)%3
    for (int t = blockIdx.x; t < N_TILES_K; t += gridDim.x) {
        const int i0 = t * TILE_K;
        const int rows = min(TILE_K, N_ITEMS_K - i0);
        const int tn = t + gridDim.x;
        const int tnc = (tn < N_TILES_K) ? tn : t;   // clamped: redundant, unread
        int segreg = 0;
        if (tid < rows) segreg = seg[i0 + tid];

        // rotated buffer byte-offsets for e%3 = 0,1,2
        uint32_t bb[3];
        bb[0] = rot * 32768u;
        bb[1] = (rot == 2) ? 0u : (rot + 1) * 32768u;
        bb[2] = (rot == 0) ? 65536u : (rot - 1) * 32768u;

        float acc[2][8][4];
        #pragma unroll
        for (int m = 0; m < 2; m++)
            #pragma unroll
            for (int n = 0; n < 8; n++)
                #pragma unroll
                for (int i = 0; i < 4; i++) acc[m][n][i] = 0.f;

        #pragma unroll
        for (int e = 0; e < 8; e++) {
            CP_WAIT1();
            __syncthreads();
            const uint32_t bo = bb[e % 3];

            #pragma unroll
            for (int sl = 0; sl < 2; sl++) {
                const uint32_t offB = ((uint32_t)(4 * e + 2 * sl) ^ l6) << 4;
                const uint32_t offA = bo + (xa0 ^ ((uint32_t)sl << 6));
                float4 v00 = *(const float4*)(sm + (Arow[0] + offA - sb));
                float4 v01 = *(const float4*)(sm + (Arow[1] + offA - sb));
                uint32_t B[4][4];
                ldsm4(B[0], Bb[0] + offB);
                ldsm4(B[1], Bb[1] + offB);
                ldsm4(B[2], Bb[2] + offB);
                ldsm4(B[3], Bb[3] + offB);
                float4 v10 = *(const float4*)(sm + (Arow[2] + offA - sb));
                float4 v11 = *(const float4*)(sm + (Arow[3] + offA - sb));

                uint32_t Ah[4];
                {
                    __half2 h0 = __float22half2_rn(make_float2(v00.x, v00.y));
                    __half2 h1 = __float22half2_rn(make_float2(v01.x, v01.y));
                    __half2 h2 = __float22half2_rn(make_float2(v00.z, v00.w));
                    __half2 h3 = __float22half2_rn(make_float2(v01.z, v01.w));
                    Ah[0] = *(uint32_t*)&h0; Ah[1] = *(uint32_t*)&h1;
                    Ah[2] = *(uint32_t*)&h2; Ah[3] = *(uint32_t*)&h3;
                }
                #pragma unroll
                for (int j = 0; j < 4; j++) {
                    mma16816(acc[0][2*j],   Ah, B[j][0], B[j][1]);
                    mma16816(acc[0][2*j+1], Ah, B[j][2], B[j][3]);
                }
                {
                    __half2 h0 = __float22half2_rn(make_float2(v10.x, v10.y));
                    __half2 h1 = __float22half2_rn(make_float2(v11.x, v11.y));
                    __half2 h2 = __float22half2_rn(make_float2(v10.z, v10.w));
                    __half2 h3 = __float22half2_rn(make_float2(v11.z, v11.w));
                    Ah[0] = *(uint32_t*)&h0; Ah[1] = *(uint32_t*)&h1;
                    Ah[2] = *(uint32_t*)&h2; Ah[3] = *(uint32_t*)&h3;
                }
                #pragma unroll
                for (int j = 0; j < 4; j++) {
                    mma16816(acc[1][2*j],   Ah, B[j][0], B[j][1]);
                    mma16816(acc[1][2*j+1], Ah, B[j][2], B[j][3]);
                }
            }

            // refill: eighth e+2 (this tile) or next tile's e-6
            if (e < 6) issue_e(t,   e + 2, bb[(e + 2) % 3]);
            else       issue_e(tnc, e - 6, bb[(e + 2) % 3]);
            CP_COMMIT();
        }

        // ---- epilogue: +b, relu, h fp16 (dedicated region) ----
        {
            const int c0 = nq * 64 + 2 * tq;
            #pragma unroll
            for (int m = 0; m < 2; m++) {
                char* base0 = sm + SM_H16 + (size_t)(R + 16 * m) * 256;
                char* base1 = base0 + 8 * 256;
                #pragma unroll
                for (int n = 0; n < 8; n++) {
                    const int c = c0 + n * 8;
                    const uint32_t so = ((uint32_t)((nq * 8 + n) ^ g) << 4)
                                      + (uint32_t)tq * 4u;
                    const float b0 = b_s[c], b1 = b_s[c + 1];
                    __half2 u0 = __float22half2_rn(make_float2(
                        fmaxf(acc[m][n][0] + b0, 0.f), fmaxf(acc[m][n][1] + b1, 0.f)));
                    __half2 u1 = __float22half2_rn(make_float2(
                        fmaxf(acc[m][n][2] + b0, 0.f), fmaxf(acc[m][n][3] + b1, 0.f)));
                    *(__half2*)(base0 + so) = u0;
                    *(__half2*)(base1 + so) = u1;
                }
            }
        }
        if (tid < rows) seg_s[tid] = segreg;
        __syncthreads();

        // ---- segment reduce: 8 row-groups (32 rows) x 64 col-pairs (half2) ----
        {
            const int cp   = tid & 63;           // column pair: cols 2cp, 2cp+1
            const int r0   = (tid >> 6) * 32;
            const int rend = min(rows, r0 + 32);
            const uint32_t slot = (uint32_t)(cp >> 2);
            const uint32_t intra = (uint32_t)(cp & 3) * 4u;
            if (r0 < rows) {
                float a0 = 0.f, a1 = 0.f;
                int cur = seg_s[r0];
                const int c = 2 * cp;
                for (int r = r0; r < rend; r++) {
                    int s = seg_s[r];
                    if (s != cur) {
                        atomicAdd(&g_scratch[(size_t)cur * BAG_K + c], a0);
                        atomicAdd(&g_scratch[(size_t)cur * BAG_K + c + 1], a1);
                        a0 = 0.f; a1 = 0.f;
                        cur = s;
                    }
                    __half2 hv = *(const __half2*)(sm + SM_H16 + (size_t)r * 256
                               + (((slot ^ (uint32_t)(r & 7)) << 4) + intra));
                    float2 fv = __half22float2(hv);
                    a0 += fv.x; a1 += fv.y;
                }
                atomicAdd(&g_scratch[(size_t)cur * BAG_K + c], a0);
                atomicAdd(&g_scratch[(size_t)cur * BAG_K + c + 1], a1);
            }
        }
        // no sync: next tile's eighth-syncs guard all reuse; cp.async for the
        // next tile's first two eighths is already streaming in the background.
        rot = (rot + 2) % 3;   // 8 eighths consumed -> rotation advances by 8%3
    }
    CP_WAIT0();   // drain outstanding groups before smem is released
}

// ---- per-column batch stats over the 50k bag means (vectorized) ----
__global__ void __launch_bounds__(256) stats_kernel(const int* __restrict__ blen)
{
    __shared__ float4 red_s[8][32];
    __shared__ float4 red_ss[8][32];
    const int c4 = threadIdx.x & 31;
    const int rs = threadIdx.x >> 5;
    float4 s  = make_float4(0.f, 0.f, 0.f, 0.f);
    float4 ss = make_float4(0.f, 0.f, 0.f, 0.f);
    const float4* gs = (const float4*)g_scratch;
    for (int r = blockIdx.x * 8 + rs; r < N_BAGS_K; r += gridDim.x * 8) {
        float inv = 1.f / (float)max(blen[r], 1);
        float4 v = gs[(size_t)r * 32 + c4];
        v.x *= inv; v.y *= inv; v.z *= inv; v.w *= inv;
        s.x += v.x;  s.y += v.y;  s.z += v.z;  s.w += v.w;
        ss.x += v.x * v.x; ss.y += v.y * v.y; ss.z += v.z * v.z; ss.w += v.w * v.w;
    }
    red_s[rs][c4]  = s;
    red_ss[rs][c4] = ss;
    __syncthreads();
    if (rs == 0) {
        #pragma unroll
        for (int i = 1; i < 8; i++) {
            float4 a = red_s[i][c4], b = red_ss[i][c4];
            s.x += a.x; s.y += a.y; s.z += a.z; s.w += a.w;
            ss.x += b.x; ss.y += b.y; ss.z += b.z; ss.w += b.w;
        }
        float* dst  = &g_scratch[(size_t)N_BAGS_K * BAG_K + c4 * 4];
        float* dst2 = &g_scratch[(size_t)N_BAGS_K * BAG_K + BAG_K + c4 * 4];
        atomicAdd(dst + 0, s.x);  atomicAdd(dst + 1, s.y);
        atomicAdd(dst + 2, s.z);  atomicAdd(dst + 3, s.w);
        atomicAdd(dst2 + 0, ss.x); atomicAdd(dst2 + 1, ss.y);
        atomicAdd(dst2 + 2, ss.z); atomicAdd(dst2 + 3, ss.w);
    }
}

// ---- normalize; also restores segment-sum scratch to zero for next launch ----
__global__ void __launch_bounds__(256) norm_kernel(const int* __restrict__ blen,
                                                   const float* __restrict__ gamma,
                                                   const float* __restrict__ beta,
                                                   float* __restrict__ out)
{
    const int c4 = threadIdx.x & 31;
    const int rs = threadIdx.x >> 5;
    const float inv_n = 1.f / (float)N_BAGS_K;
    float4 m = *(const float4*)&g_scratch[(size_t)N_BAGS_K * BAG_K + c4 * 4];
    float4 e = *(const float4*)&g_scratch[(size_t)N_BAGS_K * BAG_K + BAG_K + c4 * 4];
    float4 ga = ((const float4*)gamma)[c4];
    float4 be = ((const float4*)beta)[c4];
    float4 mean, scale;
    mean.x = m.x * inv_n; mean.y = m.y * inv_n;
    mean.z = m.z * inv_n; mean.w = m.w * inv_n;
    scale.x = rsqrtf(e.x * inv_n - mean.x * mean.x + EPS_K) * ga.x;
    scale.y = rsqrtf(e.y * inv_n - mean.y * mean.y + EPS_K) * ga.y;
    scale.z = rsqrtf(e.z * inv_n - mean.z * mean.z + EPS_K) * ga.z;
    scale.w = rsqrtf(e.w * inv_n - mean.w * mean.w + EPS_K) * ga.w;
    float4* gs = (float4*)g_scratch;
    float4* o4 = (float4*)out;
    const float4 z4 = make_float4(0.f, 0.f, 0.f, 0.f);
    for (int r = blockIdx.x * 8 + rs; r < N_BAGS_K; r += gridDim.x * 8) {
        float inv = 1.f / (float)max(blen[r], 1);
        float4 v = gs[(size_t)r * 32 + c4];
        float4 o;
        o.x = (v.x * inv - mean.x) * scale.x + be.x;
        o.y = (v.y * inv - mean.y) * scale.y + be.y;
        o.z = (v.z * inv - mean.z) * scale.z + be.z;
        o.w = (v.w * inv - mean.w) * scale.w + be.w;
        o4[(size_t)r * 32 + c4] = o;
        gs[(size_t)r * 32 + c4] = z4;   // restore zeros for next launch/replay
    }
}

extern "C" void kernel_launch(void* const* d_in, const int* in_sizes, int n_in,
                              void* d_out, int out_size)
{
    const float* x     = (const float*)d_in[0];
    const float* W     = (const float*)d_in[1];
    const float* bvec  = (const float*)d_in[2];
    const float* gamma = (const float*)d_in[3];
    const float* beta  = (const float*)d_in[4];
    const int*   seg   = (const int*)d_in[5];
    const int*   blen  = (const int*)d_in[6];
    float*       out   = (float*)d_out;

    (void)in_sizes; (void)n_in; (void)out_size;

    // only the tiny stats slots need zeroing; the big sums region is
    // statically zero-initialized and restored by norm_kernel each launch
    void* scratch = nullptr;
    cudaGetSymbolAddress(&scratch, g_scratch);
    cudaMemsetAsync((char*)scratch + sizeof(float) * (size_t)N_BAGS_K * BAG_K, 0,
                    sizeof(float) * 2 * BAG_K, 0);

    int dev = 0, nsm = 148;
    cudaGetDevice(&dev);
    cudaDeviceGetAttribute(&nsm, cudaDevAttrMultiProcessorCount, dev);

    cudaFuncSetAttribute(fused_gemm_seg_kernel,
                         cudaFuncAttributeMaxDynamicSharedMemorySize, SMEM_DYN);
    fused_gemm_seg_kernel<<<nsm, 512, SMEM_DYN>>>(x, W, bvec, seg);
    stats_kernel<<<256, 256>>>(blen);
    norm_kernel<<<1024, 256>>>(blen, gamma, beta, out);
}